// round 9
// baseline (speedup 1.0000x reference)
#include <cuda_runtime.h>
#include <cuda_bf16.h>

#define HH 256
#define WW 256
#define NIMG (64*21)
#define TILE_X 128
#define TILE_Y 64
#define SROWS (TILE_Y + 8)     // 72 input rows
#define SSTRIDE (TILE_X + 8)   // 136 elements per row
#define SPAIR (SROWS / 2)      // 36 interleaved pair-rows
#define PSTRIDE (2 * SSTRIDE)  // 272 floats per pair-row (1088 B)

// Packed f32x2 FMA (Blackwell FFMA2) — ptxas never emits this from C++.
__device__ __forceinline__ float2 ffma2(float2 a, float2 b, float2 c) {
    float2 d;
    asm("fma.rn.f32x2 %0, %1, %2, %3;"
        : "=l"(reinterpret_cast<unsigned long long&>(d))
        : "l"(reinterpret_cast<unsigned long long&>(a)),
          "l"(reinterpret_cast<unsigned long long&>(b)),
          "l"(reinterpret_cast<unsigned long long&>(c)));
    return d;
}

// Gaussian symmetric: g[j] == g[8-j] bit-exactly.
#define GG(j) gg[((j) < 5) ? (j) : (8 - (j))]

__global__ __launch_bounds__(256, 4)
void heatmap_sepconv_kernel(const int* __restrict__ coords,
                            const float* __restrict__ noise,
                            const float* __restrict__ k2d,
                            float* __restrict__ out)
{
    __shared__ float sk[81];
    // Row-pair interleaved tile: sin_[p*PSTRIDE + 2*x + h] = input row (2p+h), col x.
    __shared__ __align__(16) float sin_[SPAIR * PSTRIDE];  // 39168 B

    const int tid = threadIdx.x;
    const int img = blockIdx.z;
    const int x0 = blockIdx.x * TILE_X;
    const int y0 = blockIdx.y * TILE_Y;

    if (tid < 81) sk[tid] = k2d[tid];

    const float* __restrict__ np = noise + (size_t)img * (HH * WW);

    // ---- Main tile load: each thread loads a row-PAIR chunk and writes it
    //      interleaved. gya is always even, so both rows share one bounds check.
    {
        const int px = tid & 31;
        const int py = tid >> 5;
        const int lcol = px << 2;
        #pragma unroll
        for (int s = 0; s < 5; s++) {
            const int pr = s * 8 + py;
            if (s < 4 || py < SPAIR - 32) {     // pr < 36
                const int gya = y0 - 4 + 2 * pr;  // even
                float4 a = make_float4(0.f, 0.f, 0.f, 0.f);
                float4 b = make_float4(0.f, 0.f, 0.f, 0.f);
                if (gya >= 0 && gya < HH) {
                    const float* gp = np + gya * WW + x0 + lcol;
                    a = *(const float4*)(gp);
                    b = *(const float4*)(gp + WW);  // gya+1 <= 255 whenever gya valid
                }
                float* dst = &sin_[pr * PSTRIDE + 2 * (4 + lcol)];
                *(float4*)(dst)     = make_float4(a.x, b.x, a.y, b.y);
                *(float4*)(dst + 4) = make_float4(a.z, b.z, a.w, b.w);
            }
        }
    }
    // ---- Halo columns: 72 rows x (4 left + 4 right), scalar, interleaved addr ----
    for (int e = tid; e < SROWS * 8; e += 256) {
        const int row = e >> 3;
        const int c = e & 7;
        const int ic = (c < 4) ? c : (128 + c);
        const int gy = y0 - 4 + row;
        const int gx = x0 - 4 + ic;
        float v = 0.f;
        if (gy >= 0 && gy < HH && gx >= 0 && gx < WW) v = np[gy * WW + gx];
        sin_[(row >> 1) * PSTRIDE + 2 * ic + (row & 1)] = v;
    }
    __syncthreads();

    // ---- Peak injection (noise unscaled -> peak 100x; 0.01 applied at store) ----
    if (tid == 0) {
        const int cx = coords[2 * img];
        const int cy = coords[2 * img + 1];
        const int lx = cx - (x0 - 4);
        const int ly = cy - (y0 - 4);
        if (lx >= 0 && lx < SSTRIDE && ly >= 0 && ly < SROWS)
            sin_[(ly >> 1) * PSTRIDE + 2 * lx + (ly & 1)] = 100.0f / sk[40];
    }
    __syncthreads();

    // 1D gaussian = row sums of 2D kernel; 5 packed symmetric taps.
    float2 gg[5];
    #pragma unroll
    for (int i = 0; i < 5; i++) {
        float s = 0.f;
        #pragma unroll
        for (int j = 0; j < 9; j++) s += sk[i * 9 + j];
        gg[i] = make_float2(s, s);
    }

    const int tx = tid & 31;
    const int ty = tid >> 5;
    const int cbase = tx * 4;
    const int r0 = ty * 8;          // even
    const int p0 = r0 >> 1;         // first input pair-row for this thread

    // Column-packed accumulators: A[r][0]=(c0,c1), A[r][1]=(c2,c3).
    float2 A[8][2];
    #pragma unroll
    for (int r = 0; r < 8; r++) {
        A[r][0] = make_float2(0.f, 0.f);
        A[r][1] = make_float2(0.f, 0.f);
    }

    // Stream 8 interleaved pair-rows (16 input rows).
    #pragma unroll
    for (int t = 0; t < 8; t++) {
        const float* rp = &sin_[(p0 + t) * PSTRIDE + 2 * cbase];
        // 6 LDS.128 -> 12 (rowA, rowB) pairs directly in even-aligned reg pairs.
        float2 v2[12];
        #pragma unroll
        for (int q = 0; q < 6; q++) {
            float4 w = *(const float4*)(rp + 4 * q);
            v2[2 * q]     = make_float2(w.x, w.y);
            v2[2 * q + 1] = make_float2(w.z, w.w);
        }

        // Horizontal pass: hp[cc] = (h_rowA[cc], h_rowB[cc]) via 9 FFMA2 each.
        float2 hp[4];
        #pragma unroll
        for (int cc = 0; cc < 4; cc++) {
            float2 s = make_float2(0.f, 0.f);
            #pragma unroll
            for (int j = 0; j < 9; j++) s = ffma2(GG(j), v2[cc + j], s);
            hp[cc] = s;
        }

        // Column re-pack for vertical pass (8 MOVs per t, only packing left).
        float2 hap0 = make_float2(hp[0].x, hp[1].x);
        float2 hap1 = make_float2(hp[2].x, hp[3].x);
        float2 hbp0 = make_float2(hp[0].y, hp[1].y);
        float2 hbp1 = make_float2(hp[2].y, hp[3].y);

        // Vertical accumulation: taps ia = 2t - r (rowA), ib = 2t+1 - r (rowB).
        #pragma unroll
        for (int r = 0; r < 8; r++) {
            const int ia = 2 * t - r;
            if (ia >= 0 && ia <= 8) {
                A[r][0] = ffma2(GG(ia), hap0, A[r][0]);
                A[r][1] = ffma2(GG(ia), hap1, A[r][1]);
            }
            const int ib = 2 * t + 1 - r;
            if (ib >= 0 && ib <= 8) {
                A[r][0] = ffma2(GG(ib), hbp0, A[r][0]);
                A[r][1] = ffma2(GG(ib), hbp1, A[r][1]);
            }
        }
    }

    // Store: deferred 0.01 scale + ReLU.
    const size_t obase = (size_t)img * (HH * WW);
    #pragma unroll
    for (int r = 0; r < 8; r++) {
        const int gy = y0 + r0 + r;
        float4 ov = make_float4(fmaxf(A[r][0].x, 0.f) * 0.01f,
                                fmaxf(A[r][0].y, 0.f) * 0.01f,
                                fmaxf(A[r][1].x, 0.f) * 0.01f,
                                fmaxf(A[r][1].y, 0.f) * 0.01f);
        *(float4*)(out + obase + (size_t)gy * WW + x0 + cbase) = ov;
    }
}

extern "C" void kernel_launch(void* const* d_in, const int* in_sizes, int n_in,
                              void* d_out, int out_size)
{
    const int* coords = nullptr;
    const float* noise = nullptr;
    const float* k2d = nullptr;
    for (int i = 0; i < n_in; i++) {
        if (in_sizes[i] == 81)            k2d    = (const float*)d_in[i];
        else if (in_sizes[i] == 64*21*2)  coords = (const int*)d_in[i];
        else                              noise  = (const float*)d_in[i];
    }

    dim3 grid(WW / TILE_X, HH / TILE_Y, NIMG);
    heatmap_sepconv_kernel<<<grid, 256>>>(coords, noise, k2d, (float*)d_out);
}

// round 10
// speedup vs baseline: 1.1665x; 1.1665x over previous
#include <cuda_runtime.h>
#include <cuda_bf16.h>

#define HH 256
#define WW 256
#define NIMG (64*21)
#define TILE_X 128
#define TILE_Y 64
#define SROWS (TILE_Y + 8)     // 72 input rows
#define SSTRIDE (TILE_X + 8)   // 136 logical columns
#define SPAIR (SROWS / 2)      // 36 interleaved pair-rows
#define PSTRIDE (2 * SSTRIDE)  // 272 floats per pair-row

// Packed f32x2 FMA (Blackwell FFMA2) — ptxas never emits this from C++.
__device__ __forceinline__ float2 ffma2(float2 a, float2 b, float2 c) {
    float2 d;
    asm("fma.rn.f32x2 %0, %1, %2, %3;"
        : "=l"(reinterpret_cast<unsigned long long&>(d))
        : "l"(reinterpret_cast<unsigned long long&>(a)),
          "l"(reinterpret_cast<unsigned long long&>(b)),
          "l"(reinterpret_cast<unsigned long long&>(c)));
    return d;
}

// Gaussian symmetric: g[j] == g[8-j] bit-exactly.
#define GG(j) gg[((j) < 5) ? (j) : (8 - (j))]

__global__ __launch_bounds__(256, 4)
void heatmap_sepconv_kernel(const int* __restrict__ coords,
                            const float* __restrict__ noise,
                            const float* __restrict__ k2d,
                            float* __restrict__ out)
{
    __shared__ float sk[81];
    // Pair-interleaved tile: sin_[p*PSTRIDE + 2*x + h] = input row (2p+h), col x.
    __shared__ __align__(16) float sin_[SPAIR * PSTRIDE];  // 39168 B

    const int tid = threadIdx.x;
    const int img = blockIdx.z;
    const int x0 = blockIdx.x * TILE_X;
    const int y0 = blockIdx.y * TILE_Y;

    if (tid < 81) sk[tid] = k2d[tid];

    const float* __restrict__ np = noise + (size_t)img * (HH * WW);

    // ---- Main tile load: each thread loads a (rowA,rowB)x4col chunk per sweep,
    //      writes it interleaved. gya is even -> one bounds check per pair. ----
    {
        const int px = tid & 31;
        const int py = tid >> 5;
        const int lcol = px << 2;
        #pragma unroll
        for (int s = 0; s < 5; s++) {
            const int pr = s * 8 + py;
            if (s < 4 || py < SPAIR - 32) {       // pr < 36
                const int gya = y0 - 4 + 2 * pr;   // even
                float4 a = make_float4(0.f, 0.f, 0.f, 0.f);
                float4 b = make_float4(0.f, 0.f, 0.f, 0.f);
                if (gya >= 0 && gya < HH) {
                    const float* gp = np + gya * WW + x0 + lcol;
                    a = *(const float4*)(gp);
                    b = *(const float4*)(gp + WW);
                }
                float* dst = &sin_[pr * PSTRIDE + 2 * (4 + lcol)];
                *(float4*)(dst)     = make_float4(a.x, b.x, a.y, b.y);
                *(float4*)(dst + 4) = make_float4(a.z, b.z, a.w, b.w);
            }
        }
    }
    // ---- Halo columns: 72 rows x (4 left + 4 right), scalar, interleaved ----
    for (int e = tid; e < SROWS * 8; e += 256) {
        const int row = e >> 3;
        const int c = e & 7;
        const int ic = (c < 4) ? c : (128 + c);
        const int gy = y0 - 4 + row;
        const int gx = x0 - 4 + ic;
        float v = 0.f;
        if (gy >= 0 && gy < HH && gx >= 0 && gx < WW) v = np[gy * WW + gx];
        sin_[(row >> 1) * PSTRIDE + 2 * ic + (row & 1)] = v;
    }
    __syncthreads();

    // ---- Peak injection (noise unscaled -> peak 100x; 0.01 applied at store) ----
    if (tid == 0) {
        const int cx = coords[2 * img];
        const int cy = coords[2 * img + 1];
        const int lx = cx - (x0 - 4);
        const int ly = cy - (y0 - 4);
        if (lx >= 0 && lx < SSTRIDE && ly >= 0 && ly < SROWS)
            sin_[(ly >> 1) * PSTRIDE + 2 * lx + (ly & 1)] = 100.0f / sk[40];
    }
    __syncthreads();

    // 1D gaussian = row sums of 2D kernel; 5 packed symmetric taps.
    float2 gg[5];
    #pragma unroll
    for (int i = 0; i < 5; i++) {
        float s = 0.f;
        #pragma unroll
        for (int j = 0; j < 9; j++) s += sk[i * 9 + j];
        gg[i] = make_float2(s, s);
    }

    // Thread owns 2 columns x 16 output rows: conflict-free 16B lane stride.
    const int g  = tid & 63;        // column pair index: output cols 2g, 2g+1
    const int ty = tid >> 6;        // 0..3
    const int r0 = ty * 16;         // first output row
    const int p0 = ty * 8;          // first input pair-row

    // Accumulators: acc[r] = (out[r, 2g], out[r, 2g+1]).
    float2 A[16];
    #pragma unroll
    for (int r = 0; r < 16; r++) A[r] = make_float2(0.f, 0.f);

    // Stream 12 pair-rows (24 haloed input rows).
    const float* rp = &sin_[p0 * PSTRIDE + 4 * g];  // input col 2g, 16B aligned
    #pragma unroll
    for (int t = 0; t < 12; t++) {
        // 5 LDS.128 (immediate offsets) -> 10 (rowA,rowB) pairs, zero MOVs.
        float2 v2[10];
        #pragma unroll
        for (int q = 0; q < 5; q++) {
            float4 w = *(const float4*)(rp + 4 * q);
            v2[2 * q]     = make_float2(w.x, w.y);
            v2[2 * q + 1] = make_float2(w.z, w.w);
        }
        rp += PSTRIDE;

        // Horizontal: s0 = (hA_c, hB_c), s1 = (hA_c+1, hB_c+1). 18 FFMA2.
        float2 s0 = make_float2(0.f, 0.f);
        float2 s1 = make_float2(0.f, 0.f);
        #pragma unroll
        for (int j = 0; j < 9; j++) {
            s0 = ffma2(GG(j), v2[j], s0);
            s1 = ffma2(GG(j), v2[j + 1], s1);
        }
        // Column re-pack for the vertical pass (the only packing left).
        float2 ha = make_float2(s0.x, s1.x);   // row 2t   halo-row horizontal
        float2 hb = make_float2(s0.y, s1.y);   // row 2t+1

        // Vertical: taps ia = 2t - r, ib = 2t+1 - r, valid in [0,8].
        #pragma unroll
        for (int r = 0; r < 16; r++) {
            const int ia = 2 * t - r;
            if (ia >= 0 && ia <= 8) A[r] = ffma2(GG(ia), ha, A[r]);
            const int ib = 2 * t + 1 - r;
            if (ib >= 0 && ib <= 8) A[r] = ffma2(GG(ib), hb, A[r]);
        }
    }

    // Store: deferred 0.01 scale + ReLU; STG.64, fully coalesced.
    float* op = out + (size_t)img * (HH * WW) + (size_t)(y0 + r0) * WW + x0 + 2 * g;
    #pragma unroll
    for (int r = 0; r < 16; r++) {
        float2 ov = make_float2(fmaxf(A[r].x, 0.f) * 0.01f,
                                fmaxf(A[r].y, 0.f) * 0.01f);
        *(float2*)op = ov;
        op += WW;
    }
}

extern "C" void kernel_launch(void* const* d_in, const int* in_sizes, int n_in,
                              void* d_out, int out_size)
{
    const int* coords = nullptr;
    const float* noise = nullptr;
    const float* k2d = nullptr;
    for (int i = 0; i < n_in; i++) {
        if (in_sizes[i] == 81)            k2d    = (const float*)d_in[i];
        else if (in_sizes[i] == 64*21*2)  coords = (const int*)d_in[i];
        else                              noise  = (const float*)d_in[i];
    }

    dim3 grid(WW / TILE_X, HH / TILE_Y, NIMG);
    heatmap_sepconv_kernel<<<grid, 256>>>(coords, noise, k2d, (float*)d_out);
}